// round 2
// baseline (speedup 1.0000x reference)
#include <cuda_runtime.h>
#include <math.h>

#define T 2048
#define D 1024
#define E 8
#define H 2048
#define TOPK 2

#define BM 128
#define BN 128
#define BK 8

// ---------------- device scratch (static, no allocations) ----------------
__device__ int   g_counts[E];
__device__ int   g_offsets[E + 1];
__device__ int   g_fill[E];
__device__ int   g_route_idx[T][TOPK];
__device__ float g_route_w[T][TOPK];
__device__ int   g_slot_token[T * TOPK];
__device__ float g_slot_w[T * TOPK];
__device__ float g_h[(size_t)T * TOPK * H];   // 32 MB: silu(x @ w1^T) per routed slot

// ---------------- K0: zero output + counters ----------------
__global__ void zero_kernel(float* __restrict__ out) {
    int i = blockIdx.x * blockDim.x + threadIdx.x;   // grid covers T*D/4 float4s
    float4 z = make_float4(0.f, 0.f, 0.f, 0.f);
    reinterpret_cast<float4*>(out)[i] = z;
    if (blockIdx.x == 0 && threadIdx.x < E) {
        g_counts[threadIdx.x] = 0;
        g_fill[threadIdx.x] = 0;
    }
}

// ---------------- K1: gating (one block per token, one warp per expert) ----------------
__global__ void gate_kernel(const float* __restrict__ x,
                            const float* __restrict__ gw,
                            const float* __restrict__ bias) {
    int t = blockIdx.x;
    int lane = threadIdx.x & 31;
    int w = threadIdx.x >> 5;              // expert index, 8 warps
    const float* xr = x + (size_t)t * D;
    const float* gr = gw + (size_t)w * D;
    float s = 0.f;
    for (int d = lane; d < D; d += 32) s += xr[d] * gr[d];
    #pragma unroll
    for (int o = 16; o; o >>= 1) s += __shfl_xor_sync(0xffffffffu, s, o);
    __shared__ float sc[E];
    if (lane == 0) sc[w] = 1.f / (1.f + expf(-(s + bias[w])));
    __syncthreads();
    if (threadIdx.x == 0) {
        // top-2, lowest-index wins ties (matches jax.lax.top_k)
        int i0 = 0; float v0 = sc[0];
        for (int e = 1; e < E; e++) if (sc[e] > v0) { v0 = sc[e]; i0 = e; }
        int i1 = -1; float v1 = -1e30f;
        for (int e = 0; e < E; e++) if (e != i0 && sc[e] > v1) { v1 = sc[e]; i1 = e; }
        float inv = 1.f / (v0 + v1 + 1e-6f);
        g_route_idx[t][0] = i0; g_route_idx[t][1] = i1;
        g_route_w[t][0] = v0 * inv; g_route_w[t][1] = v1 * inv;
        atomicAdd(&g_counts[i0], 1);
        atomicAdd(&g_counts[i1], 1);
    }
}

// ---------------- K2: trivial prefix scan over 8 experts ----------------
__global__ void scan_kernel() {
    if (blockIdx.x == 0 && threadIdx.x == 0) {
        int acc = 0;
        for (int e = 0; e < E; e++) { g_offsets[e] = acc; acc += g_counts[e]; }
        g_offsets[E] = acc;
    }
}

// ---------------- K3: scatter tokens into per-expert compacted slot lists ----------------
__global__ void scatter_kernel() {
    int t = blockIdx.x * blockDim.x + threadIdx.x;
    if (t >= T) return;
    #pragma unroll
    for (int k = 0; k < TOPK; k++) {
        int e = g_route_idx[t][k];
        int pos = g_offsets[e] + atomicAdd(&g_fill[e], 1);
        g_slot_token[pos] = t;
        g_slot_w[pos] = g_route_w[t][k];
    }
}

// ---------------- K4: gathered SGEMM1 + SiLU:  h = silu(x[tok] @ w1[e]^T) ----------------
// NT gemm: A rows = x (K-major, K=D), B rows = w1[e] (K-major). 128x128x8 tile, 256 thr.
__global__ __launch_bounds__(256) void gemm1_kernel(const float* __restrict__ x,
                                                    const float* __restrict__ w1) {
    int e = blockIdx.z;
    int cnt = g_counts[e];
    int m0 = blockIdx.y * BM;
    if (m0 >= cnt) return;
    int off = g_offsets[e];
    int n0 = blockIdx.x * BN;
    int tid = threadIdx.x;

    __shared__ float As[BK][BM + 4];
    __shared__ float Bs[BK][BN + 4];

    int lrow = tid >> 1;              // 0..127
    int lcol = (tid & 1) * 4;         // 0 or 4
    int aslot = m0 + lrow;
    bool avalid = aslot < cnt;
    int tok = avalid ? g_slot_token[off + aslot] : 0;
    const float* aptr = x + (size_t)tok * D + lcol;
    const float* bptr = w1 + ((size_t)e * H + (n0 + lrow)) * D + lcol;

    float acc[8][8];
    #pragma unroll
    for (int i = 0; i < 8; i++)
        #pragma unroll
        for (int j = 0; j < 8; j++) acc[i][j] = 0.f;

    int mb = (tid >> 4) * 8;
    int nb = (tid & 15) * 8;

    for (int k0 = 0; k0 < D; k0 += BK) {
        float4 a4 = avalid ? *reinterpret_cast<const float4*>(aptr + k0)
                           : make_float4(0.f, 0.f, 0.f, 0.f);
        float4 b4 = *reinterpret_cast<const float4*>(bptr + k0);
        As[lcol + 0][lrow] = a4.x; As[lcol + 1][lrow] = a4.y;
        As[lcol + 2][lrow] = a4.z; As[lcol + 3][lrow] = a4.w;
        Bs[lcol + 0][lrow] = b4.x; Bs[lcol + 1][lrow] = b4.y;
        Bs[lcol + 2][lrow] = b4.z; Bs[lcol + 3][lrow] = b4.w;
        __syncthreads();
        #pragma unroll
        for (int k = 0; k < BK; k++) {
            float ra[8], rb[8];
            #pragma unroll
            for (int i = 0; i < 8; i++) ra[i] = As[k][mb + i];
            #pragma unroll
            for (int j = 0; j < 8; j++) rb[j] = Bs[k][nb + j];
            #pragma unroll
            for (int i = 0; i < 8; i++)
                #pragma unroll
                for (int j = 0; j < 8; j++) acc[i][j] += ra[i] * rb[j];
        }
        __syncthreads();
    }

    #pragma unroll
    for (int i = 0; i < 8; i++) {
        int slot = m0 + mb + i;
        if (slot < cnt) {
            float* hrow = g_h + (size_t)(off + slot) * H + (n0 + nb);
            #pragma unroll
            for (int j = 0; j < 8; j++) {
                float v = acc[i][j];
                hrow[j] = v / (1.f + expf(-v));   // silu
            }
        }
    }
}

// ---------------- K5: SGEMM2 + weighted combine:  out[tok] += w * (h @ w2[e]^T) ----------------
__global__ __launch_bounds__(256) void gemm2_kernel(const float* __restrict__ w2,
                                                    float* __restrict__ out) {
    int e = blockIdx.z;
    int cnt = g_counts[e];
    int m0 = blockIdx.y * BM;
    if (m0 >= cnt) return;
    int off = g_offsets[e];
    int n0 = blockIdx.x * BN;
    int tid = threadIdx.x;

    __shared__ float As[BK][BM + 4];
    __shared__ float Bs[BK][BN + 4];

    int lrow = tid >> 1;
    int lcol = (tid & 1) * 4;
    int aslot = m0 + lrow;
    bool avalid = aslot < cnt;
    const float* aptr = g_h + (size_t)(off + (avalid ? aslot : 0)) * H + lcol;
    const float* bptr = w2 + ((size_t)e * D + (n0 + lrow)) * H + lcol;

    float acc[8][8];
    #pragma unroll
    for (int i = 0; i < 8; i++)
        #pragma unroll
        for (int j = 0; j < 8; j++) acc[i][j] = 0.f;

    int mb = (tid >> 4) * 8;
    int nb = (tid & 15) * 8;

    for (int k0 = 0; k0 < H; k0 += BK) {
        float4 a4 = avalid ? *reinterpret_cast<const float4*>(aptr + k0)
                           : make_float4(0.f, 0.f, 0.f, 0.f);
        float4 b4 = *reinterpret_cast<const float4*>(bptr + k0);
        As[lcol + 0][lrow] = a4.x; As[lcol + 1][lrow] = a4.y;
        As[lcol + 2][lrow] = a4.z; As[lcol + 3][lrow] = a4.w;
        Bs[lcol + 0][lrow] = b4.x; Bs[lcol + 1][lrow] = b4.y;
        Bs[lcol + 2][lrow] = b4.z; Bs[lcol + 3][lrow] = b4.w;
        __syncthreads();
        #pragma unroll
        for (int k = 0; k < BK; k++) {
            float ra[8], rb[8];
            #pragma unroll
            for (int i = 0; i < 8; i++) ra[i] = As[k][mb + i];
            #pragma unroll
            for (int j = 0; j < 8; j++) rb[j] = Bs[k][nb + j];
            #pragma unroll
            for (int i = 0; i < 8; i++)
                #pragma unroll
                for (int j = 0; j < 8; j++) acc[i][j] += ra[i] * rb[j];
        }
        __syncthreads();
    }

    #pragma unroll
    for (int i = 0; i < 8; i++) {
        int slot = m0 + mb + i;
        if (slot < cnt) {
            int tok = g_slot_token[off + slot];
            float wgt = g_slot_w[off + slot];
            float* orow = out + (size_t)tok * D + (n0 + nb);
            #pragma unroll
            for (int j = 0; j < 8; j++)
                atomicAdd(&orow[j], wgt * acc[i][j]);
        }
    }
}

// ---------------- launch ----------------
extern "C" void kernel_launch(void* const* d_in, const int* in_sizes, int n_in,
                              void* d_out, int out_size) {
    const float* x    = (const float*)d_in[0];
    const float* gw   = (const float*)d_in[1];
    const float* bias = (const float*)d_in[2];
    const float* w1   = (const float*)d_in[3];
    const float* w2   = (const float*)d_in[4];
    float* out = (float*)d_out;

    zero_kernel<<<(T * D / 4) / 256, 256>>>(out);
    gate_kernel<<<T, 256>>>(x, gw, bias);
    scan_kernel<<<1, 32>>>();
    scatter_kernel<<<(T + 255) / 256, 256>>>();
    // worst case: all tokens on one expert -> T/BM m-tiles per expert, early-exit otherwise
    gemm1_kernel<<<dim3(H / BN, T / BM, E), 256>>>(x, w1);
    gemm2_kernel<<<dim3(D / BN, T / BM, E), 256>>>(w2, out);
}